// round 5
// baseline (speedup 1.0000x reference)
#include <cuda_runtime.h>
#include <cuda_bf16.h>
#include <math.h>
#include <stdint.h>

#define N_  4
#define T_  4096
#define D_  1024
#define H_  1536
#define M_  (N_*T_)       // 16384 rows
#define G2H (2*H_)        // 3072
#define TC  256           // scan chunk length
#define NC  (T_/TC)       // 16 chunks

// -------- scratch (device globals; no allocation allowed) --------
__device__ float g_gx  [(size_t)M_*G2H];   // x @ W_in^T ; gate half holds gelu(gate) (fused)
__device__ float g_xbc [(size_t)M_*H_];    // conv output
__device__ float g_alpha[(size_t)M_*H_];
__device__ float g_xs  [(size_t)M_*H_];    // xs, then overwritten with gelu(gate)*h in scan p3
__device__ float g_cA  [N_*NC*H_];
__device__ float g_cB  [N_*NC*H_];

// ======================= mma.sync helpers =======================
__device__ __forceinline__ uint32_t smem_u32(const void* p) {
    uint32_t a;
    asm("{ .reg .u64 t; cvta.to.shared.u64 t, %1; cvt.u32.u64 %0, t; }" : "=r"(a) : "l"(p));
    return a;
}
__device__ __forceinline__ void ldmx4(uint32_t* r, uint32_t a) {
    asm volatile("ldmatrix.sync.aligned.m8n8.x4.shared.b16 {%0,%1,%2,%3}, [%4];"
        : "=r"(r[0]), "=r"(r[1]), "=r"(r[2]), "=r"(r[3]) : "r"(a));
}
__device__ __forceinline__ void mma16816(float* d, const uint32_t* a, const uint32_t* b) {
    asm volatile("mma.sync.aligned.m16n8k16.row.col.f32.bf16.bf16.f32 "
        "{%0,%1,%2,%3}, {%4,%5,%6,%7}, {%8,%9}, {%0,%1,%2,%3};"
        : "+f"(d[0]), "+f"(d[1]), "+f"(d[2]), "+f"(d[3])
        : "r"(a[0]), "r"(a[1]), "r"(a[2]), "r"(a[3]), "r"(b[0]), "r"(b[1]));
}
__device__ __forceinline__ float sigmoidf_(float v) { return 1.f / (1.f + expf(-v)); }

// ================== bf16x3 mma.sync GEMM: C[M,Nn]=A[M,K]*B[Nn,K]^T ==================
// Block tile 128x128x32, 256 threads (8 warps: 4(m) x 2(n)), warp tile 32x64.
// SMEM rows padded to 80B. 3-stage pipeline; split/STS overlapped between MMA halves.
// EPI: 0 = plain store, 1 = gelu on first-half cols (GEMM1), 2 = fused ew (GEMM2)
#define BKB    80
#define AH_OFF 0
#define AL_OFF 10240
#define BH_OFF 20480
#define BL_OFF 30720
#define STAGE  40960
#define GEMM_SMEM (3*STAGE)   // 122880

__device__ __forceinline__ void store_split(char* hi, char* lo, int tid, const float4* r) {
#pragma unroll
    for (int i = 0; i < 4; i++) {
        int idx = i * 256 + tid;
        int row = idx >> 3, c4 = idx & 7;
        float4 f = r[i];
        __nv_bfloat162 h0 = __floats2bfloat162_rn(f.x, f.y);
        __nv_bfloat162 h1 = __floats2bfloat162_rn(f.z, f.w);
        float2 r0 = __bfloat1622float2(h0);
        float2 r1 = __bfloat1622float2(h1);
        __nv_bfloat162 l0 = __floats2bfloat162_rn(f.x - r0.x, f.y - r0.y);
        __nv_bfloat162 l1 = __floats2bfloat162_rn(f.z - r1.x, f.w - r1.y);
        uint32_t off = (uint32_t)(row * BKB + c4 * 8);
        uint2 hv, lv;
        hv.x = *(uint32_t*)&h0; hv.y = *(uint32_t*)&h1;
        lv.x = *(uint32_t*)&l0; lv.y = *(uint32_t*)&l1;
        *(uint2*)(hi + off) = hv;
        *(uint2*)(lo + off) = lv;
    }
}

__device__ __forceinline__ void compute_kt(float acc[2][8][4], uint32_t sa, uint32_t sbb, int kt) {
    uint32_t ah[2][4], al[2][4], bh[4][4], bl[4][4];
#pragma unroll
    for (int mt = 0; mt < 2; mt++) {
        ldmx4(ah[mt], sa + mt * (16 * BKB) + kt * 32);
        ldmx4(al[mt], sa + AL_OFF + mt * (16 * BKB) + kt * 32);
    }
#pragma unroll
    for (int n2 = 0; n2 < 4; n2++) {
        ldmx4(bh[n2], sbb + n2 * (16 * BKB) + kt * 32);
        ldmx4(bl[n2], sbb + (BL_OFF - BH_OFF) + n2 * (16 * BKB) + kt * 32);
    }
#pragma unroll
    for (int mt = 0; mt < 2; mt++)
#pragma unroll
        for (int nt = 0; nt < 8; nt++) {
            uint32_t* bph = &bh[nt >> 1][(nt & 1) * 2];
            uint32_t* bpl = &bl[nt >> 1][(nt & 1) * 2];
            mma16816(acc[mt][nt], ah[mt], bph);
            mma16816(acc[mt][nt], ah[mt], bpl);
            mma16816(acc[mt][nt], al[mt], bph);
        }
}

template<int EPI>
__global__ __launch_bounds__(256)
void gemm_mma(const float* __restrict__ A, const float* __restrict__ B,
              float* __restrict__ C,
              const float* __restrict__ xbc, const float* __restrict__ bg,
              const float* __restrict__ fbase,
              float* __restrict__ alpha_o, float* __restrict__ xs_o,
              int K, int lda, int ldb, int ldc)
{
    extern __shared__ char sm[];
    const int tid = threadIdx.x;
    const int lid = tid & 31, wid = tid >> 5;
    const int wm = wid >> 1, wn = wid & 1;   // 4 x 2 warp grid
    const int bm = blockIdx.y * 128;
    const int bn = blockIdx.x * 128;

    // per-thread row pointers for the staging loads
    const int rbase = tid >> 3, c4 = tid & 7;
    const float* Arow[4]; const float* Brow[4];
#pragma unroll
    for (int i = 0; i < 4; i++) {
        int row = rbase + i * 32;
        Arow[i] = A + (size_t)(bm + row) * lda + c4 * 4;
        int grow = (EPI == 2) ? ((row & 1) * H_ + (bn >> 1) + (row >> 1)) : (bn + row);
        Brow[i] = B + (size_t)grow * ldb + c4 * 4;
    }

    float acc[2][8][4];
#pragma unroll
    for (int i = 0; i < 2; i++)
#pragma unroll
        for (int j = 0; j < 8; j++)
#pragma unroll
            for (int q = 0; q < 4; q++) acc[i][j][q] = 0.f;

    // prologue: chunk 0 -> stage 0; chunk 1 -> regs
    float4 ra[4], rb[4];
#pragma unroll
    for (int i = 0; i < 4; i++) { ra[i] = *(const float4*)(Arow[i]); rb[i] = *(const float4*)(Brow[i]); }
    store_split(sm + AH_OFF, sm + AL_OFF, tid, ra);
    store_split(sm + BH_OFF, sm + BL_OFF, tid, rb);
    const int KT = K >> 5;
    if (KT > 1) {
#pragma unroll
        for (int i = 0; i < 4; i++) { ra[i] = *(const float4*)(Arow[i] + 32); rb[i] = *(const float4*)(Brow[i] + 32); }
    }

    const uint32_t sb = smem_u32(sm);
    const uint32_t a_base = sb + (uint32_t)((wm * 32 + (lid & 15)) * BKB + ((lid >> 4) & 1) * 16);
    const uint32_t b_base = sb + BH_OFF +
        (uint32_t)((wn * 64 + (lid & 7) + ((lid >> 4) & 1) * 8) * BKB + ((lid >> 3) & 1) * 16);

    int cur = 0;
    for (int c = 0; c < KT; c++) {
        const int nxt = (cur == 2) ? 0 : cur + 1;
        __syncthreads();
        const uint32_t sa  = a_base + cur * STAGE;
        const uint32_t sbb = b_base + cur * STAGE;
        compute_kt(acc, sa, sbb, 0);
        if (c + 1 < KT) {
            store_split(sm + nxt * STAGE + AH_OFF, sm + nxt * STAGE + AL_OFF, tid, ra);
            store_split(sm + nxt * STAGE + BH_OFF, sm + nxt * STAGE + BL_OFF, tid, rb);
        }
        if (c + 2 < KT) {
#pragma unroll
            for (int i = 0; i < 4; i++) {
                ra[i] = *(const float4*)(Arow[i] + (c + 2) * 32);
                rb[i] = *(const float4*)(Brow[i] + (c + 2) * 32);
            }
        }
        compute_kt(acc, sa, sbb, 1);
        cur = nxt;
    }

    const int r0 = bm + wm * 32 + (lid >> 2);

    if (EPI == 2) {
        // fused ew: cols are interleaved (forget_h, inp_h) pairs; h = col/2
        const int hbase = (bn >> 1) + wn * 32 + (lid & 3);
        float sp8[8], bgf[8], bgi[8];
#pragma unroll
        for (int nt = 0; nt < 8; nt++) {
            int h = hbase + nt * 4;
            float fb = fbase[h];
            sp8[nt] = fmaxf(fb, 0.f) + log1pf(expf(-fabsf(fb)));
            bgf[nt] = bg[h]; bgi[nt] = bg[H_ + h];
        }
#pragma unroll
        for (int mt = 0; mt < 2; mt++) {
            int row = r0 + mt * 16;
#pragma unroll
            for (int nt = 0; nt < 8; nt++) {
                int h = hbase + nt * 4;
                {
                    float forget = acc[mt][nt][0] + bgf[nt];
                    float inp    = acc[mt][nt][1] + bgi[nt];
                    float a = expf(-8.f * sp8[nt] * sigmoidf_(forget));
                    float beta = sqrtf(1.f - a * a + 1e-6f);
                    float xv = beta * sigmoidf_(inp) * xbc[(size_t)row * H_ + h];
                    alpha_o[(size_t)row * H_ + h] = a;
                    xs_o[(size_t)row * H_ + h] = xv;
                }
                {
                    float forget = acc[mt][nt][2] + bgf[nt];
                    float inp    = acc[mt][nt][3] + bgi[nt];
                    float a = expf(-8.f * sp8[nt] * sigmoidf_(forget));
                    float beta = sqrtf(1.f - a * a + 1e-6f);
                    float xv = beta * sigmoidf_(inp) * xbc[(size_t)(row + 8) * H_ + h];
                    alpha_o[(size_t)(row + 8) * H_ + h] = a;
                    xs_o[(size_t)(row + 8) * H_ + h] = xv;
                }
            }
        }
        return;
    }

    // plain / gelu epilogue
    const bool dg = (EPI == 1) && (bn < H_);
    const int cbase = bn + wn * 64 + (lid & 3) * 2;
#pragma unroll
    for (int mt = 0; mt < 2; mt++) {
        const int row = r0 + mt * 16;
#pragma unroll
        for (int nt = 0; nt < 8; nt++) {
            const int col = cbase + nt * 8;
            float2 v0 = make_float2(acc[mt][nt][0], acc[mt][nt][1]);
            float2 v1 = make_float2(acc[mt][nt][2], acc[mt][nt][3]);
            if (dg) {
                v0.x = 0.5f * v0.x * (1.f + erff(v0.x * 0.70710678118654752f));
                v0.y = 0.5f * v0.y * (1.f + erff(v0.y * 0.70710678118654752f));
                v1.x = 0.5f * v1.x * (1.f + erff(v1.x * 0.70710678118654752f));
                v1.y = 0.5f * v1.y * (1.f + erff(v1.y * 0.70710678118654752f));
            }
            *(float2*)(C + (size_t)row * ldc + col) = v0;
            *(float2*)(C + (size_t)(row + 8) * ldc + col) = v1;
        }
    }
}

// -------- depthwise causal conv K=4 over t; reads B-half of g_gx --------
__global__ void conv_kernel(const float* __restrict__ cw, const float* __restrict__ cb)
{
    long long idx = (long long)blockIdx.x * blockDim.x + threadIdx.x;
    if (idx >= (long long)M_ * H_) return;
    int h = (int)(idx % H_);
    long long m = idx / H_;
    int t = (int)(m % T_);
    long long n = m / T_;
    float acc = cb[h];
    const float* w = cw + h * 4;
#pragma unroll
    for (int k = 0; k < 4; k++) {
        int tt = t - 3 + k;
        if (tt >= 0)
            acc = fmaf(w[k], g_gx[((size_t)(n * T_ + tt)) * G2H + H_ + h], acc);
    }
    g_xbc[idx] = acc;
}

// -------- chunked linear scan: h_t = a_t * h_{t-1} + x_t --------
__global__ void scan_p1()
{
    int h = blockIdx.x * 128 + threadIdx.x;
    int c = blockIdx.y, n = blockIdx.z;
    size_t base = ((size_t)(n * T_ + c * TC)) * H_ + h;
    float A = 1.f, Bv = 0.f;
#pragma unroll 4
    for (int t = 0; t < TC; t++) {
        float a = g_alpha[base + (size_t)t * H_];
        float x = g_xs   [base + (size_t)t * H_];
        Bv = fmaf(a, Bv, x);
        A *= a;
    }
    int ci = (n * NC + c) * H_ + h;
    g_cA[ci] = A;
    g_cB[ci] = Bv;
}

__global__ void scan_p2()
{
    int h = blockIdx.x * 128 + threadIdx.x;
    int n = blockIdx.y;
    float carry = 0.f;
    for (int c = 0; c < NC; c++) {
        int i = (n * NC + c) * H_ + h;
        float a = g_cA[i], b = g_cB[i];
        g_cB[i] = carry;
        carry = fmaf(a, carry, b);
    }
}

__global__ void scan_p3()
{
    int h = blockIdx.x * 128 + threadIdx.x;
    int c = blockIdx.y, n = blockIdx.z;
    size_t base  = ((size_t)(n * T_ + c * TC)) * H_ + h;
    size_t gbase = ((size_t)(n * T_ + c * TC)) * G2H + h;
    float hp = g_cB[(n * NC + c) * H_ + h];
#pragma unroll 4
    for (int t = 0; t < TC; t++) {
        float a = g_alpha[base + (size_t)t * H_];
        float x = g_xs   [base + (size_t)t * H_];
        hp = fmaf(a, hp, x);
        float g = g_gx[gbase + (size_t)t * G2H];   // gelu(gate), fused in GEMM1
        g_xs[base + (size_t)t * H_] = hp * g;
    }
}

// -------- launch --------
extern "C" void kernel_launch(void* const* d_in, const int* in_sizes, int n_in,
                              void* d_out, int out_size)
{
    const float* x      = (const float*)d_in[0];
    const float* W_in   = (const float*)d_in[1];
    const float* conv_w = (const float*)d_in[2];
    const float* conv_b = (const float*)d_in[3];
    const float* W_g    = (const float*)d_in[4];
    const float* b_g    = (const float*)d_in[5];
    const float* fbase  = (const float*)d_in[6];
    const float* W_out  = (const float*)d_in[7];
    float* out = (float*)d_out;

    float *gx, *xbc, *alp, *xs;
    cudaGetSymbolAddress((void**)&gx,  g_gx);
    cudaGetSymbolAddress((void**)&xbc, g_xbc);
    cudaGetSymbolAddress((void**)&alp, g_alpha);
    cudaGetSymbolAddress((void**)&xs,  g_xs);

    cudaFuncSetAttribute(gemm_mma<0>, cudaFuncAttributeMaxDynamicSharedMemorySize, GEMM_SMEM);
    cudaFuncSetAttribute(gemm_mma<1>, cudaFuncAttributeMaxDynamicSharedMemorySize, GEMM_SMEM);
    cudaFuncSetAttribute(gemm_mma<2>, cudaFuncAttributeMaxDynamicSharedMemorySize, GEMM_SMEM);

    const long long tot = (long long)M_ * H_;
    const int EB = 256;
    const int eg = (int)((tot + EB - 1) / EB);

    // 1) gx = x @ W_in^T; gelu applied to gate half in epilogue
    gemm_mma<1><<<dim3(G2H/128, M_/128), 256, GEMM_SMEM>>>(
        x, W_in, gx, nullptr, nullptr, nullptr, nullptr, nullptr, D_, D_, D_, G2H);
    // 2) depthwise causal conv on B-half
    conv_kernel<<<eg, EB>>>(conv_w, conv_b);
    // 3) fg = xbc @ W_g^T + b_g, fused ew epilogue -> alpha, xs
    gemm_mma<2><<<dim3(G2H/128, M_/128), 256, GEMM_SMEM>>>(
        xbc, W_g, nullptr, xbc, b_g, fbase, alp, xs, H_, H_, H_, 0);
    // 4) linear scan (3 phases), p3 fuses gelu(gate)*h into g_xs
    scan_p1<<<dim3(H_/128, NC, N_), 128>>>();
    scan_p2<<<dim3(H_/128, N_), 128>>>();
    scan_p3<<<dim3(H_/128, NC, N_), 128>>>();
    // 5) out = (gelu(gate)*h) @ W_out^T
    gemm_mma<0><<<dim3(D_/128, M_/128), 256, GEMM_SMEM>>>(
        xs, W_out, out, nullptr, nullptr, nullptr, nullptr, nullptr, H_, H_, H_, D_);
}

// round 6
// speedup vs baseline: 1.1269x; 1.1269x over previous
#include <cuda_runtime.h>
#include <cuda_bf16.h>
#include <math.h>
#include <stdint.h>

#define N_  4
#define T_  4096
#define D_  1024
#define H_  1536
#define M_  (N_*T_)       // 16384 rows
#define G2H (2*H_)        // 3072
#define TC  128           // scan chunk length
#define NC  (T_/TC)       // 32 chunks

// -------- scratch (device globals; no allocation allowed) --------
__device__ float g_gx  [(size_t)M_*G2H];   // x @ W_in^T ; gate half holds gelu(gate) (fused)
__device__ float g_xbc [(size_t)M_*H_];    // conv output
__device__ float g_alpha[(size_t)M_*H_];
__device__ float g_xs  [(size_t)M_*H_];    // xs, then overwritten with gelu(gate)*h in scan p3
__device__ float g_cA  [N_*NC*H_];
__device__ float g_cB  [N_*NC*H_];

// ======================= mma.sync helpers =======================
__device__ __forceinline__ uint32_t smem_u32(const void* p) {
    uint32_t a;
    asm("{ .reg .u64 t; cvta.to.shared.u64 t, %1; cvt.u32.u64 %0, t; }" : "=r"(a) : "l"(p));
    return a;
}
__device__ __forceinline__ void ldmx4(uint32_t* r, uint32_t a) {
    asm volatile("ldmatrix.sync.aligned.m8n8.x4.shared.b16 {%0,%1,%2,%3}, [%4];"
        : "=r"(r[0]), "=r"(r[1]), "=r"(r[2]), "=r"(r[3]) : "r"(a));
}
__device__ __forceinline__ void mma16816(float* d, const uint32_t* a, const uint32_t* b) {
    asm volatile("mma.sync.aligned.m16n8k16.row.col.f32.bf16.bf16.f32 "
        "{%0,%1,%2,%3}, {%4,%5,%6,%7}, {%8,%9}, {%0,%1,%2,%3};"
        : "+f"(d[0]), "+f"(d[1]), "+f"(d[2]), "+f"(d[3])
        : "r"(a[0]), "r"(a[1]), "r"(a[2]), "r"(a[3]), "r"(b[0]), "r"(b[1]));
}
__device__ __forceinline__ float sigmoidf_(float v) { return 1.f / (1.f + expf(-v)); }

// ================== bf16x3 mma.sync GEMM: C[M,Nn]=A[M,K]*B[Nn,K]^T ==================
// Block tile 128x128x32, 256 threads (8 warps: 4(m) x 2(n)), warp tile 32x64.
// SMEM rows padded to 80B. 2-stage pipeline (81920B -> 2 CTAs/SM).
// EPI: 0 = plain store, 1 = gelu on first-half cols (GEMM1), 2 = fused ew (GEMM2)
#define BKB    80
#define AH_OFF 0
#define AL_OFF 10240
#define BH_OFF 20480
#define BL_OFF 30720
#define STAGE  40960
#define GEMM_SMEM (2*STAGE)   // 81920

__device__ __forceinline__ void store_split(char* hi, char* lo, int tid, const float4* r) {
#pragma unroll
    for (int i = 0; i < 4; i++) {
        int idx = i * 256 + tid;
        int row = idx >> 3, c4 = idx & 7;
        float4 f = r[i];
        __nv_bfloat162 h0 = __floats2bfloat162_rn(f.x, f.y);
        __nv_bfloat162 h1 = __floats2bfloat162_rn(f.z, f.w);
        float2 r0 = __bfloat1622float2(h0);
        float2 r1 = __bfloat1622float2(h1);
        __nv_bfloat162 l0 = __floats2bfloat162_rn(f.x - r0.x, f.y - r0.y);
        __nv_bfloat162 l1 = __floats2bfloat162_rn(f.z - r1.x, f.w - r1.y);
        uint32_t off = (uint32_t)(row * BKB + c4 * 8);
        uint2 hv, lv;
        hv.x = *(uint32_t*)&h0; hv.y = *(uint32_t*)&h1;
        lv.x = *(uint32_t*)&l0; lv.y = *(uint32_t*)&l1;
        *(uint2*)(hi + off) = hv;
        *(uint2*)(lo + off) = lv;
    }
}

__device__ __forceinline__ void compute_kt(float acc[2][8][4], uint32_t sa, uint32_t sbb, int kt) {
    uint32_t ah[2][4], al[2][4], bh[4][4], bl[4][4];
#pragma unroll
    for (int mt = 0; mt < 2; mt++) {
        ldmx4(ah[mt], sa + mt * (16 * BKB) + kt * 32);
        ldmx4(al[mt], sa + AL_OFF + mt * (16 * BKB) + kt * 32);
    }
#pragma unroll
    for (int n2 = 0; n2 < 4; n2++) {
        ldmx4(bh[n2], sbb + n2 * (16 * BKB) + kt * 32);
        ldmx4(bl[n2], sbb + (BL_OFF - BH_OFF) + n2 * (16 * BKB) + kt * 32);
    }
#pragma unroll
    for (int mt = 0; mt < 2; mt++)
#pragma unroll
        for (int nt = 0; nt < 8; nt++) {
            uint32_t* bph = &bh[nt >> 1][(nt & 1) * 2];
            uint32_t* bpl = &bl[nt >> 1][(nt & 1) * 2];
            mma16816(acc[mt][nt], ah[mt], bph);
            mma16816(acc[mt][nt], ah[mt], bpl);
            mma16816(acc[mt][nt], al[mt], bph);
        }
}

template<int EPI>
__global__ __launch_bounds__(256)
void gemm_mma(const float* __restrict__ A, const float* __restrict__ B,
              float* __restrict__ C,
              const float* __restrict__ xbc, const float* __restrict__ bg,
              const float* __restrict__ fbase,
              float* __restrict__ alpha_o, float* __restrict__ xs_o,
              int K, int lda, int ldb, int ldc)
{
    extern __shared__ char sm[];
    const int tid = threadIdx.x;
    const int lid = tid & 31, wid = tid >> 5;
    const int wm = wid >> 1, wn = wid & 1;   // 4 x 2 warp grid
    const int bm = blockIdx.y * 128;
    const int bn = blockIdx.x * 128;

    // per-thread row pointers for the staging loads (B rows permuted for EPI==2)
    const int rbase = tid >> 3, c4 = tid & 7;
    const float* Arow[4]; const float* Brow[4];
#pragma unroll
    for (int i = 0; i < 4; i++) {
        int row = rbase + i * 32;
        Arow[i] = A + (size_t)(bm + row) * lda + c4 * 4;
        int grow = (EPI == 2) ? ((row & 1) * H_ + (bn >> 1) + (row >> 1)) : (bn + row);
        Brow[i] = B + (size_t)grow * ldb + c4 * 4;
    }

    float acc[2][8][4];
#pragma unroll
    for (int i = 0; i < 2; i++)
#pragma unroll
        for (int j = 0; j < 8; j++)
#pragma unroll
            for (int q = 0; q < 4; q++) acc[i][j][q] = 0.f;

    // prologue: chunk 0 -> stage 0
    float4 ra[4], rb[4];
#pragma unroll
    for (int i = 0; i < 4; i++) { ra[i] = *(const float4*)(Arow[i]); rb[i] = *(const float4*)(Brow[i]); }
    store_split(sm + AH_OFF, sm + AL_OFF, tid, ra);
    store_split(sm + BH_OFF, sm + BL_OFF, tid, rb);
    __syncthreads();

    const uint32_t sb = smem_u32(sm);
    const uint32_t a_base = sb + (uint32_t)((wm * 32 + (lid & 15)) * BKB + ((lid >> 4) & 1) * 16);
    const uint32_t b_base = sb + BH_OFF +
        (uint32_t)((wn * 64 + (lid & 7) + ((lid >> 4) & 1) * 8) * BKB + ((lid >> 3) & 1) * 16);

    const int KT = K >> 5;
    for (int c = 0; c < KT; c++) {
        const int cur = c & 1;
        const bool more = (c + 1 < KT);
        if (more) {
#pragma unroll
            for (int i = 0; i < 4; i++) {
                ra[i] = *(const float4*)(Arow[i] + (c + 1) * 32);
                rb[i] = *(const float4*)(Brow[i] + (c + 1) * 32);
            }
        }
        const uint32_t sa  = a_base + cur * STAGE;
        const uint32_t sbb = b_base + cur * STAGE;
        compute_kt(acc, sa, sbb, 0);
        compute_kt(acc, sa, sbb, 1);
        if (more) {
            const int nxt = (c + 1) & 1;
            store_split(sm + nxt * STAGE + AH_OFF, sm + nxt * STAGE + AL_OFF, tid, ra);
            store_split(sm + nxt * STAGE + BH_OFF, sm + nxt * STAGE + BL_OFF, tid, rb);
        }
        __syncthreads();
    }

    const int r0 = bm + wm * 32 + (lid >> 2);

    if (EPI == 2) {
        // fused ew: output cols are interleaved (forget_h, inp_h) pairs
        const int hbase = (bn >> 1) + wn * 32 + (lid & 3);
        float sp8[8], bgf[8], bgi[8];
#pragma unroll
        for (int nt = 0; nt < 8; nt++) {
            int h = hbase + nt * 4;
            float fb = fbase[h];
            sp8[nt] = fmaxf(fb, 0.f) + log1pf(expf(-fabsf(fb)));
            bgf[nt] = bg[h]; bgi[nt] = bg[H_ + h];
        }
#pragma unroll
        for (int mt = 0; mt < 2; mt++) {
            int row = r0 + mt * 16;
#pragma unroll
            for (int nt = 0; nt < 8; nt++) {
                int h = hbase + nt * 4;
                {
                    float forget = acc[mt][nt][0] + bgf[nt];
                    float inp    = acc[mt][nt][1] + bgi[nt];
                    float a = expf(-8.f * sp8[nt] * sigmoidf_(forget));
                    float beta = sqrtf(1.f - a * a + 1e-6f);
                    float xv = beta * sigmoidf_(inp) * xbc[(size_t)row * H_ + h];
                    alpha_o[(size_t)row * H_ + h] = a;
                    xs_o[(size_t)row * H_ + h] = xv;
                }
                {
                    float forget = acc[mt][nt][2] + bgf[nt];
                    float inp    = acc[mt][nt][3] + bgi[nt];
                    float a = expf(-8.f * sp8[nt] * sigmoidf_(forget));
                    float beta = sqrtf(1.f - a * a + 1e-6f);
                    float xv = beta * sigmoidf_(inp) * xbc[(size_t)(row + 8) * H_ + h];
                    alpha_o[(size_t)(row + 8) * H_ + h] = a;
                    xs_o[(size_t)(row + 8) * H_ + h] = xv;
                }
            }
        }
        return;
    }

    // plain / gelu epilogue
    const bool dg = (EPI == 1) && (bn < H_);
    const int cbase = bn + wn * 64 + (lid & 3) * 2;
#pragma unroll
    for (int mt = 0; mt < 2; mt++) {
        const int row = r0 + mt * 16;
#pragma unroll
        for (int nt = 0; nt < 8; nt++) {
            const int col = cbase + nt * 8;
            float2 v0 = make_float2(acc[mt][nt][0], acc[mt][nt][1]);
            float2 v1 = make_float2(acc[mt][nt][2], acc[mt][nt][3]);
            if (dg) {
                v0.x = 0.5f * v0.x * (1.f + erff(v0.x * 0.70710678118654752f));
                v0.y = 0.5f * v0.y * (1.f + erff(v0.y * 0.70710678118654752f));
                v1.x = 0.5f * v1.x * (1.f + erff(v1.x * 0.70710678118654752f));
                v1.y = 0.5f * v1.y * (1.f + erff(v1.y * 0.70710678118654752f));
            }
            *(float2*)(C + (size_t)row * ldc + col) = v0;
            *(float2*)(C + (size_t)(row + 8) * ldc + col) = v1;
        }
    }
}

// -------- depthwise causal conv K=4 over t; reads B-half of g_gx --------
__global__ void conv_kernel(const float* __restrict__ cw, const float* __restrict__ cb)
{
    long long idx = (long long)blockIdx.x * blockDim.x + threadIdx.x;
    if (idx >= (long long)M_ * H_) return;
    int h = (int)(idx % H_);
    long long m = idx / H_;
    int t = (int)(m % T_);
    long long n = m / T_;
    float acc = cb[h];
    const float* w = cw + h * 4;
#pragma unroll
    for (int k = 0; k < 4; k++) {
        int tt = t - 3 + k;
        if (tt >= 0)
            acc = fmaf(w[k], g_gx[((size_t)(n * T_ + tt)) * G2H + H_ + h], acc);
    }
    g_xbc[idx] = acc;
}

// -------- chunked linear scan: h_t = a_t * h_{t-1} + x_t --------
__global__ void scan_p1()
{
    int h = blockIdx.x * 128 + threadIdx.x;
    int c = blockIdx.y, n = blockIdx.z;
    size_t base = ((size_t)(n * T_ + c * TC)) * H_ + h;
    float A = 1.f, Bv = 0.f;
#pragma unroll 4
    for (int t = 0; t < TC; t++) {
        float a = g_alpha[base + (size_t)t * H_];
        float x = g_xs   [base + (size_t)t * H_];
        Bv = fmaf(a, Bv, x);
        A *= a;
    }
    int ci = (n * NC + c) * H_ + h;
    g_cA[ci] = A;
    g_cB[ci] = Bv;
}

__global__ void scan_p2()
{
    int h = blockIdx.x * 128 + threadIdx.x;
    int n = blockIdx.y;
    float carry = 0.f;
    for (int c = 0; c < NC; c++) {
        int i = (n * NC + c) * H_ + h;
        float a = g_cA[i], b = g_cB[i];
        g_cB[i] = carry;
        carry = fmaf(a, carry, b);
    }
}

__global__ void scan_p3()
{
    int h = blockIdx.x * 128 + threadIdx.x;
    int c = blockIdx.y, n = blockIdx.z;
    size_t base  = ((size_t)(n * T_ + c * TC)) * H_ + h;
    size_t gbase = ((size_t)(n * T_ + c * TC)) * G2H + h;
    float hp = g_cB[(n * NC + c) * H_ + h];
#pragma unroll 4
    for (int t = 0; t < TC; t++) {
        float a = g_alpha[base + (size_t)t * H_];
        float x = g_xs   [base + (size_t)t * H_];
        hp = fmaf(a, hp, x);
        float g = g_gx[gbase + (size_t)t * G2H];   // gelu(gate), fused in GEMM1
        g_xs[base + (size_t)t * H_] = hp * g;
    }
}

// -------- launch --------
extern "C" void kernel_launch(void* const* d_in, const int* in_sizes, int n_in,
                              void* d_out, int out_size)
{
    const float* x      = (const float*)d_in[0];
    const float* W_in   = (const float*)d_in[1];
    const float* conv_w = (const float*)d_in[2];
    const float* conv_b = (const float*)d_in[3];
    const float* W_g    = (const float*)d_in[4];
    const float* b_g    = (const float*)d_in[5];
    const float* fbase  = (const float*)d_in[6];
    const float* W_out  = (const float*)d_in[7];
    float* out = (float*)d_out;

    float *gx, *xbc, *alp, *xs;
    cudaGetSymbolAddress((void**)&gx,  g_gx);
    cudaGetSymbolAddress((void**)&xbc, g_xbc);
    cudaGetSymbolAddress((void**)&alp, g_alpha);
    cudaGetSymbolAddress((void**)&xs,  g_xs);

    cudaFuncSetAttribute(gemm_mma<0>, cudaFuncAttributeMaxDynamicSharedMemorySize, GEMM_SMEM);
    cudaFuncSetAttribute(gemm_mma<1>, cudaFuncAttributeMaxDynamicSharedMemorySize, GEMM_SMEM);
    cudaFuncSetAttribute(gemm_mma<2>, cudaFuncAttributeMaxDynamicSharedMemorySize, GEMM_SMEM);

    const long long tot = (long long)M_ * H_;
    const int EB = 256;
    const int eg = (int)((tot + EB - 1) / EB);

    // 1) gx = x @ W_in^T; gelu applied to gate half in epilogue
    gemm_mma<1><<<dim3(G2H/128, M_/128), 256, GEMM_SMEM>>>(
        x, W_in, gx, nullptr, nullptr, nullptr, nullptr, nullptr, D_, D_, D_, G2H);
    // 2) depthwise causal conv on B-half
    conv_kernel<<<eg, EB>>>(conv_w, conv_b);
    // 3) fg = xbc @ W_g^T + b_g, fused ew epilogue -> alpha, xs
    gemm_mma<2><<<dim3(G2H/128, M_/128), 256, GEMM_SMEM>>>(
        xbc, W_g, nullptr, xbc, b_g, fbase, alp, xs, H_, H_, H_, 0);
    // 4) linear scan (3 phases), p3 fuses gelu(gate)*h into g_xs
    scan_p1<<<dim3(H_/128, NC, N_), 128>>>();
    scan_p2<<<dim3(H_/128, N_), 128>>>();
    scan_p3<<<dim3(H_/128, NC, N_), 128>>>();
    // 5) out = (gelu(gate)*h) @ W_out^T
    gemm_mma<0><<<dim3(D_/128, M_/128), 256, GEMM_SMEM>>>(
        xs, W_out, out, nullptr, nullptr, nullptr, nullptr, nullptr, H_, H_, H_, D_);
}